// round 3
// baseline (speedup 1.0000x reference)
#include <cuda_runtime.h>
#include <cuda_fp16.h>
#include <mma.h>
#include <math.h>
#include <stdint.h>

using namespace nvcuda;

// ---------------- problem constants ----------------
constexpr int Bn = 2, Tn = 2048, Dn = 1024, Hn = 16, DHn = 64, Fn = 4096;
constexpr int Mrows = Bn * Tn;           // 4096 token rows

// ---------------- scratch (static device globals; no allocations) ----------------
__device__ __align__(256) __half g_srcH[Mrows * Dn];
__device__ __align__(256) __half g_wq[Dn * Dn];
__device__ __align__(256) __half g_wk[Dn * Dn];
__device__ __align__(256) __half g_wv[Dn * Dn];
__device__ __align__(256) __half g_wo[Dn * Dn];
__device__ __align__(256) __half g_w1[Fn * Dn];
__device__ __align__(256) __half g_w2[Dn * Fn];
__device__ __align__(256) __half g_q[Mrows * Dn];
__device__ __align__(256) __half g_k[Mrows * Dn];
__device__ __align__(256) __half g_v[Mrows * Dn];
__device__ __align__(256) __half g_attnH[Mrows * Dn];
__device__ __align__(256) __half g_h1[Mrows * Fn];
__device__ __align__(256) __half g_x1H[Mrows * Dn];
__device__ __align__(256) float  g_attnproj[Mrows * Dn];
__device__ __align__(256) float  g_x1[Mrows * Dn];
__device__ __align__(256) float  g_ff[Mrows * Dn];
__device__ __align__(256) unsigned char g_mask[Tn * Tn];
__device__ int g_maskmode;

// ---------------- mask dtype detection + canonicalization ----------------
__global__ void detect_mask_kernel(const unsigned int* __restrict__ w) {
    bool all01 = true, allf = true;
    for (int i = 0; i < 4096; i++) {
        unsigned int v = w[i];
        if (v > 1u) all01 = false;
        if (v != 0u && v != 0x3F800000u) allf = false;
    }
    g_maskmode = all01 ? 0 : (allf ? 1 : 2);  // 0=int32, 1=float32, 2=byte
}

__global__ void convert_mask_kernel(const void* __restrict__ raw,
                                    unsigned char* __restrict__ outm, int n) {
    int i = blockIdx.x * blockDim.x + threadIdx.x;
    if (i >= n) return;
    int mode = g_maskmode;
    unsigned char v;
    if (mode == 0)      v = (((const int*)raw)[i] != 0);
    else if (mode == 1) v = (((const float*)raw)[i] != 0.0f);
    else                v = (((const unsigned char*)raw)[i] != 0);
    outm[i] = v;
}

// ---------------- fp32 -> fp16 conversion ----------------
__global__ void cvt_f2h(const float* __restrict__ in, __half* __restrict__ out, int n) {
    int i = blockIdx.x * blockDim.x + threadIdx.x;
    int stride = gridDim.x * blockDim.x;
    int n4 = n >> 2;
    for (; i < n4; i += stride) {
        float4 v = ((const float4*)in)[i];
        ((__half2*)out)[2 * i]     = __floats2half2_rn(v.x, v.y);
        ((__half2*)out)[2 * i + 1] = __floats2half2_rn(v.z, v.w);
    }
}

// ---------------- GEMM: Y[M,N] = A[M,K] @ W[N,K]^T + bias ----------------
// Block 128x128, BK=32, 256 threads (8 warps, 2x4), warp tile 64x32 via wmma 16x16x16.
constexpr int GBM = 128, GBN = 128, GBK = 32, GLD = 40;

template<int RELU, int OUTF, int OUTH>
__global__ void gemm_bias_kernel(const __half* __restrict__ A, const __half* __restrict__ W,
                                 const float* __restrict__ bias,
                                 float* __restrict__ Cf, __half* __restrict__ Ch,
                                 int M, int N, int K) {
    __shared__ __align__(16) __half As[GBM][GLD];
    __shared__ __align__(16) __half Ws[GBN][GLD];
    __shared__ __align__(16) float  st[8][16][16];

    int tid = threadIdx.x;
    int warp = tid >> 5, lane = tid & 31;
    int bm = blockIdx.y * GBM;
    int bn = blockIdx.x * GBN;
    int wr = (warp >> 2) * 64;   // 0 or 64
    int wc = (warp & 3) * 32;    // 0,32,64,96

    wmma::fragment<wmma::accumulator, 16, 16, 16, float> acc[4][2];
    #pragma unroll
    for (int i = 0; i < 4; i++)
        #pragma unroll
        for (int j = 0; j < 2; j++) wmma::fill_fragment(acc[i][j], 0.0f);

    for (int kt = 0; kt < K; kt += GBK) {
        #pragma unroll
        for (int r = 0; r < 2; r++) {
            int chunk = tid + r * 256;          // 0..511
            int row = chunk >> 2;
            int kc  = (chunk & 3) * 8;
            *(uint4*)(&As[row][kc]) = *(const uint4*)(A + (size_t)(bm + row) * K + kt + kc);
            *(uint4*)(&Ws[row][kc]) = *(const uint4*)(W + (size_t)(bn + row) * K + kt + kc);
        }
        __syncthreads();
        #pragma unroll
        for (int kk = 0; kk < 2; kk++) {
            wmma::fragment<wmma::matrix_a, 16, 16, 16, __half, wmma::row_major> af[4];
            wmma::fragment<wmma::matrix_b, 16, 16, 16, __half, wmma::col_major> bf[2];
            #pragma unroll
            for (int i = 0; i < 4; i++)
                wmma::load_matrix_sync(af[i], &As[wr + i * 16][kk * 16], GLD);
            #pragma unroll
            for (int j = 0; j < 2; j++)
                wmma::load_matrix_sync(bf[j], &Ws[wc + j * 16][kk * 16], GLD);
            #pragma unroll
            for (int i = 0; i < 4; i++)
                #pragma unroll
                for (int j = 0; j < 2; j++)
                    wmma::mma_sync(acc[i][j], af[i], bf[j], acc[i][j]);
        }
        __syncthreads();
    }

    // epilogue: stage each 16x16 frag through per-warp smem, add bias, (relu), store
    #pragma unroll
    for (int i = 0; i < 4; i++) {
        #pragma unroll
        for (int j = 0; j < 2; j++) {
            wmma::store_matrix_sync(&st[warp][0][0], acc[i][j], 16, wmma::mem_row_major);
            __syncwarp();
            int gr0 = bm + wr + i * 16;
            int gc0 = bn + wc + j * 16;
            int rr = lane >> 1;
            int cc = (lane & 1) * 8;
            #pragma unroll
            for (int e = 0; e < 8; e++) {
                int col = cc + e;
                float v = st[warp][rr][col] + bias[gc0 + col];
                if (RELU) v = fmaxf(v, 0.0f);
                size_t idx = (size_t)(gr0 + rr) * N + gc0 + col;
                if (OUTF) Cf[idx] = v;
                if (OUTH) Ch[idx] = __float2half(v);
            }
            __syncwarp();
        }
    }
}

// ---------------- flash attention, one (b,h,qtile64) per block, 128 threads ----------------
// dynamic smem layout (bytes):
//  Qs half[64*72] @0       Ks @9216      Vs @18432    Ps @27648
//  Ss float[64*72] @36864  Os float[64*72] @55296
//  Ms uchar[64*64] @73728  m/l/scale float[64]*3 @77824   total 78592
constexpr int ATT_SMEM = 78592;

__global__ void attention_kernel(const __half* __restrict__ Q,
                                 const __half* __restrict__ Kg,
                                 const __half* __restrict__ Vg,
                                 const unsigned char* __restrict__ mask,
                                 __half* __restrict__ Out) {
    extern __shared__ __align__(16) char sm[];
    __half* Qs = (__half*)sm;
    __half* Ks = (__half*)(sm + 9216);
    __half* Vs = (__half*)(sm + 18432);
    __half* Ps = (__half*)(sm + 27648);
    float*  Ss = (float*)(sm + 36864);
    float*  Os = (float*)(sm + 55296);
    unsigned char* Ms = (unsigned char*)(sm + 73728);
    float* mrow = (float*)(sm + 77824);
    float* lrow = mrow + 64;
    float* srow = lrow + 64;

    int tid = threadIdx.x;
    int warp = tid >> 5;
    int qt = blockIdx.x, h = blockIdx.y, b = blockIdx.z;
    const size_t headoff = (size_t)h * DHn;

    // load Q tile (64 x 64 halves)
    #pragma unroll
    for (int i = 0; i < 4; i++) {
        int chunk = tid + i * 128;           // 0..511
        int r = chunk >> 3;
        int c = (chunk & 7) * 8;
        *(uint4*)(Qs + r * 72 + c) =
            *(const uint4*)(Q + ((size_t)(b * Tn + qt * 64 + r)) * Dn + headoff + c);
    }
    for (int i = tid; i < 64 * 72; i += 128) Os[i] = 0.0f;
    if (tid < 64) { mrow[tid] = -INFINITY; lrow[tid] = 0.0f; srow[tid] = 1.0f; }
    __syncthreads();

    for (int kb = 0; kb < Tn / 64; kb++) {
        // load K, V tiles + mask tile
        #pragma unroll
        for (int i = 0; i < 4; i++) {
            int chunk = tid + i * 128;
            int r = chunk >> 3;
            int c = (chunk & 7) * 8;
            size_t g = ((size_t)(b * Tn + kb * 64 + r)) * Dn + headoff + c;
            *(uint4*)(Ks + r * 72 + c) = *(const uint4*)(Kg + g);
            *(uint4*)(Vs + r * 72 + c) = *(const uint4*)(Vg + g);
        }
        #pragma unroll
        for (int i = 0; i < 2; i++) {
            int chunk = tid + i * 128;       // 0..255
            int r = chunk >> 2;
            int c = (chunk & 3) * 16;
            *(uint4*)(Ms + r * 64 + c) =
                *(const uint4*)(mask + (size_t)(qt * 64 + r) * Tn + kb * 64 + c);
        }
        __syncthreads();

        // S = Q K^T : warp handles rows [16*warp, 16*warp+16)
        {
            wmma::fragment<wmma::accumulator, 16, 16, 16, float> sacc[4];
            #pragma unroll
            for (int j = 0; j < 4; j++) wmma::fill_fragment(sacc[j], 0.0f);
            #pragma unroll
            for (int kc = 0; kc < 4; kc++) {
                wmma::fragment<wmma::matrix_a, 16, 16, 16, __half, wmma::row_major> af;
                wmma::load_matrix_sync(af, Qs + (warp * 16) * 72 + kc * 16, 72);
                #pragma unroll
                for (int j = 0; j < 4; j++) {
                    wmma::fragment<wmma::matrix_b, 16, 16, 16, __half, wmma::col_major> bf;
                    wmma::load_matrix_sync(bf, Ks + (j * 16) * 72 + kc * 16, 72);
                    wmma::mma_sync(sacc[j], af, bf, sacc[j]);
                }
            }
            #pragma unroll
            for (int j = 0; j < 4; j++)
                wmma::store_matrix_sync(Ss + (warp * 16) * 72 + j * 16, sacc[j], 72,
                                        wmma::mem_row_major);
        }
        __syncthreads();

        // online softmax: one row per thread (threads 0..63)
        if (tid < 64) {
            int r = tid;
            float mold = mrow[r];
            float mx = mold;
            #pragma unroll 8
            for (int c = 0; c < 64; c++) {
                if (!Ms[r * 64 + c]) {
                    float s = Ss[r * 72 + c] * 0.125f;
                    mx = fmaxf(mx, s);
                }
            }
            float sc;
            if (mx == -INFINITY)        sc = 1.0f;  // all masked so far; l stays 0
            else if (mold == -INFINITY) sc = 0.0f;  // first unmasked block
            else                        sc = __expf(mold - mx);
            float lnew = lrow[r] * sc;
            #pragma unroll 8
            for (int c = 0; c < 64; c++) {
                float p = 0.0f;
                if (!Ms[r * 64 + c])
                    p = __expf(Ss[r * 72 + c] * 0.125f - mx);
                lnew += p;
                Ps[r * 72 + c] = __float2half(p);
            }
            mrow[r] = mx; lrow[r] = lnew; srow[r] = sc;
        }
        __syncthreads();

        // PV : out_tile[16x64] per warp, result into Ss (reused)
        {
            wmma::fragment<wmma::accumulator, 16, 16, 16, float> pacc[4];
            #pragma unroll
            for (int j = 0; j < 4; j++) wmma::fill_fragment(pacc[j], 0.0f);
            #pragma unroll
            for (int kc = 0; kc < 4; kc++) {
                wmma::fragment<wmma::matrix_a, 16, 16, 16, __half, wmma::row_major> af;
                wmma::load_matrix_sync(af, Ps + (warp * 16) * 72 + kc * 16, 72);
                #pragma unroll
                for (int j = 0; j < 4; j++) {
                    wmma::fragment<wmma::matrix_b, 16, 16, 16, __half, wmma::row_major> bf;
                    wmma::load_matrix_sync(bf, Vs + (kc * 16) * 72 + j * 16, 72);
                    wmma::mma_sync(pacc[j], af, bf, pacc[j]);
                }
            }
            #pragma unroll
            for (int j = 0; j < 4; j++)
                wmma::store_matrix_sync(Ss + (warp * 16) * 72 + j * 16, pacc[j], 72,
                                        wmma::mem_row_major);
        }
        __syncthreads();

        // O = O * scale + PV
        for (int i = tid; i < 64 * 64; i += 128) {
            int r = i >> 6, c = i & 63;
            Os[r * 72 + c] = Os[r * 72 + c] * srow[r] + Ss[r * 72 + c];
        }
        __syncthreads();
    }

    // writeout: O / l  (l==0 -> 0, matching reference's zeroing of fully-masked rows)
    for (int i = tid; i < 64 * 64; i += 128) {
        int r = i >> 6, c = i & 63;
        float l = lrow[r];
        float o = (l > 0.0f) ? Os[r * 72 + c] / l : 0.0f;
        Out[((size_t)(b * Tn + qt * 64 + r)) * Dn + headoff + c] = __float2half(o);
    }
}

// ---------------- fused residual + LayerNorm: out = LN(x + alpha*y)*s + b ----------------
__global__ void addln_kernel(const float* __restrict__ x, const float* __restrict__ y,
                             const float* __restrict__ alphap,
                             const float* __restrict__ sc, const float* __restrict__ bi,
                             float* __restrict__ outf, __half* __restrict__ outh) {
    int row = blockIdx.x;
    int tid = threadIdx.x;
    float a = *alphap;
    float4 xv = ((const float4*)(x + (size_t)row * Dn))[tid];
    float4 yv = ((const float4*)(y + (size_t)row * Dn))[tid];
    float v0 = xv.x + a * yv.x, v1 = xv.y + a * yv.y;
    float v2 = xv.z + a * yv.z, v3 = xv.w + a * yv.w;

    __shared__ float red1[8], red2[8], bc[2];
    float s = v0 + v1 + v2 + v3;
    #pragma unroll
    for (int o = 16; o > 0; o >>= 1) s += __shfl_xor_sync(0xffffffffu, s, o);
    if ((tid & 31) == 0) red1[tid >> 5] = s;
    __syncthreads();
    if (tid == 0) {
        float t = 0;
        #pragma unroll
        for (int i = 0; i < 8; i++) t += red1[i];
        bc[0] = t * (1.0f / Dn);
    }
    __syncthreads();
    float mu = bc[0];
    float d0 = v0 - mu, d1 = v1 - mu, d2 = v2 - mu, d3 = v3 - mu;
    float q = d0 * d0 + d1 * d1 + d2 * d2 + d3 * d3;
    #pragma unroll
    for (int o = 16; o > 0; o >>= 1) q += __shfl_xor_sync(0xffffffffu, q, o);
    if ((tid & 31) == 0) red2[tid >> 5] = q;
    __syncthreads();
    if (tid == 0) {
        float t = 0;
        #pragma unroll
        for (int i = 0; i < 8; i++) t += red2[i];
        bc[1] = rsqrtf(t * (1.0f / Dn) + 1e-5f);
    }
    __syncthreads();
    float inv = bc[1];
    float4 sv = ((const float4*)sc)[tid];
    float4 bv = ((const float4*)bi)[tid];
    float o0 = d0 * inv * sv.x + bv.x;
    float o1 = d1 * inv * sv.y + bv.y;
    float o2 = d2 * inv * sv.z + bv.z;
    float o3 = d3 * inv * sv.w + bv.w;
    ((float4*)(outf + (size_t)row * Dn))[tid] = make_float4(o0, o1, o2, o3);
    if (outh) {
        ((__half2*)(outh + (size_t)row * Dn))[tid * 2]     = __floats2half2_rn(o0, o1);
        ((__half2*)(outh + (size_t)row * Dn))[tid * 2 + 1] = __floats2half2_rn(o2, o3);
    }
}

// ---------------- launch ----------------
extern "C" void kernel_launch(void* const* d_in, const int* in_sizes, int n_in,
                              void* d_out, int out_size) {
    (void)in_sizes; (void)n_in; (void)out_size;
    const float* src        = (const float*)d_in[0];
    const void*  maskraw    = d_in[1];
    const float* q_w        = (const float*)d_in[2];
    const float* q_b        = (const float*)d_in[3];
    const float* k_w        = (const float*)d_in[4];
    const float* k_b        = (const float*)d_in[5];
    const float* v_w        = (const float*)d_in[6];
    const float* v_b        = (const float*)d_in[7];
    const float* o_w        = (const float*)d_in[8];
    const float* o_b        = (const float*)d_in[9];
    const float* l1_w       = (const float*)d_in[10];
    const float* l1_b       = (const float*)d_in[11];
    const float* l2_w       = (const float*)d_in[12];
    const float* l2_b       = (const float*)d_in[13];
    const float* n1_s       = (const float*)d_in[14];
    const float* n1_b       = (const float*)d_in[15];
    const float* n2_s       = (const float*)d_in[16];
    const float* n2_b       = (const float*)d_in[17];
    const float* alpha_attn = (const float*)d_in[18];
    const float* alpha_ff   = (const float*)d_in[19];
    float* out = (float*)d_out;

    __half *srcH, *wq, *wk, *wv, *wo, *w1, *w2, *qh, *kh, *vh, *attnH, *h1, *x1H;
    float *attnproj, *x1, *ff;
    unsigned char* maskb;
    cudaGetSymbolAddress((void**)&srcH, g_srcH);
    cudaGetSymbolAddress((void**)&wq, g_wq);
    cudaGetSymbolAddress((void**)&wk, g_wk);
    cudaGetSymbolAddress((void**)&wv, g_wv);
    cudaGetSymbolAddress((void**)&wo, g_wo);
    cudaGetSymbolAddress((void**)&w1, g_w1);
    cudaGetSymbolAddress((void**)&w2, g_w2);
    cudaGetSymbolAddress((void**)&qh, g_q);
    cudaGetSymbolAddress((void**)&kh, g_k);
    cudaGetSymbolAddress((void**)&vh, g_v);
    cudaGetSymbolAddress((void**)&attnH, g_attnH);
    cudaGetSymbolAddress((void**)&h1, g_h1);
    cudaGetSymbolAddress((void**)&x1H, g_x1H);
    cudaGetSymbolAddress((void**)&attnproj, g_attnproj);
    cudaGetSymbolAddress((void**)&x1, g_x1);
    cudaGetSymbolAddress((void**)&ff, g_ff);
    cudaGetSymbolAddress((void**)&maskb, g_mask);

    cudaFuncSetAttribute(attention_kernel,
                         cudaFuncAttributeMaxDynamicSharedMemorySize, ATT_SMEM);

    // mask canonicalization
    detect_mask_kernel<<<1, 1>>>((const unsigned int*)maskraw);
    convert_mask_kernel<<<(Tn * Tn) / 256, 256>>>(maskraw, maskb, Tn * Tn);

    // fp32 -> fp16 conversions
    cvt_f2h<<<2048, 256>>>(src,  srcH, Mrows * Dn);
    cvt_f2h<<<1024, 256>>>(q_w,  wq,   Dn * Dn);
    cvt_f2h<<<1024, 256>>>(k_w,  wk,   Dn * Dn);
    cvt_f2h<<<1024, 256>>>(v_w,  wv,   Dn * Dn);
    cvt_f2h<<<1024, 256>>>(o_w,  wo,   Dn * Dn);
    cvt_f2h<<<2048, 256>>>(l1_w, w1,   Fn * Dn);
    cvt_f2h<<<2048, 256>>>(l2_w, w2,   Dn * Fn);

    // QKV projections (out fp16)
    dim3 g_qkv(Dn / GBN, Mrows / GBM);
    gemm_bias_kernel<0, 0, 1><<<g_qkv, 256>>>(srcH, wq, q_b, nullptr, qh, Mrows, Dn, Dn);
    gemm_bias_kernel<0, 0, 1><<<g_qkv, 256>>>(srcH, wk, k_b, nullptr, kh, Mrows, Dn, Dn);
    gemm_bias_kernel<0, 0, 1><<<g_qkv, 256>>>(srcH, wv, v_b, nullptr, vh, Mrows, Dn, Dn);

    // attention
    attention_kernel<<<dim3(Tn / 64, Hn, Bn), 128, ATT_SMEM>>>(qh, kh, vh, maskb, attnH);

    // O projection (out fp32)
    gemm_bias_kernel<0, 1, 0><<<g_qkv, 256>>>(attnH, wo, o_b, attnproj, nullptr, Mrows, Dn, Dn);

    // x1 = LN(src + alpha_attn * attnproj)  (fp32 + fp16 copies)
    addln_kernel<<<Mrows, 256>>>(src, attnproj, alpha_attn, n1_s, n1_b, x1, x1H);

    // FFN1: relu(x1 @ l1^T + b) -> fp16
    gemm_bias_kernel<1, 0, 1><<<dim3(Fn / GBN, Mrows / GBM), 256>>>(
        x1H, w1, l1_b, nullptr, h1, Mrows, Fn, Dn);
    // FFN2 -> fp32
    gemm_bias_kernel<0, 1, 0><<<dim3(Dn / GBN, Mrows / GBM), 256>>>(
        h1, w2, l2_b, ff, nullptr, Mrows, Dn, Fn);

    // out = LN(x1 + alpha_ff * ff)
    addln_kernel<<<Mrows, 256>>>(x1, ff, alpha_ff, n2_s, n2_b, out, nullptr);
}